// round 13
// baseline (speedup 1.0000x reference)
#include <cuda_runtime.h>
#include <cuda_fp16.h>
#include <cstdint>

// Problem dims (LLaMA-7B up-proj, AWQ w4 g128)
#define O_DIM 11008
#define I_DIM 4096
#define M_DIM 8192   // B*S
#define X_ELEMS ((size_t)M_DIM * I_DIM)

// GEMM tiling: 128x128 CTA, 8 warps of 64x32, BK=64, 3 stages
#define BM 128
#define BN 128
#define BK 64
#define KT2 (I_DIM / BK)   // 64
#define PAD 8
#define STAGES 3
#define ROWB (BK + PAD)                       // 72 halves
#define A_STAGE_BYTES (BM * ROWB * 2)         // 18432
#define B_STAGE_BYTES (BN * ROWB * 2)         // 18432
#define STAGE_BYTES (A_STAGE_BYTES + B_STAGE_BYTES)   // 36864
#define SMEM_TOTAL (STAGES * STAGE_BYTES)     // 110592

// Prep kernel split: x-stage blocks then dequant blocks
#define XSTAGE_BLOCKS ((int)(X_ELEMS / 8 / 256))            // 16384
#define DQ_BLOCKS ((O_DIM * (I_DIM / 32)) / 256)            // 5504

// Scratch: dequantized weights (O,I) fp16, staged activations (M,K) fp16
static __device__ __half g_W[(size_t)O_DIM * I_DIM];
static __device__ __half g_x[X_ELEMS];

// ---------------------------------------------------------------------------
// Fused prep: x fp32->fp16 staging AND AWQ int4 dequant in one launch.
// Blocks [0, XSTAGE_BLOCKS) stage x; blocks [XSTAGE_BLOCKS, +DQ_BLOCKS) dequant.
// ---------------------------------------------------------------------------
__global__ void __launch_bounds__(256)
prep_kernel(const float* __restrict__ xin,
            const int* __restrict__ packed,
            const float* __restrict__ s1,
            const float* __restrict__ s2) {
    if (blockIdx.x < XSTAGE_BLOCKS) {
        size_t i = ((size_t)blockIdx.x * 256 + threadIdx.x) * 8;
        const float4* p = (const float4*)(xin + i);
        float4 a = p[0], b = p[1];
        __half h[8] = {__float2half(a.x), __float2half(a.y), __float2half(a.z), __float2half(a.w),
                       __float2half(b.x), __float2half(b.y), __float2half(b.z), __float2half(b.w)};
        *(uint4*)(g_x + i) = *(const uint4*)h;
        return;
    }

    int gid = (blockIdx.x - XSTAGE_BLOCKS) * 256 + threadIdx.x;
    int o    = gid >> 7;
    int iblk = gid & 127;
    if (o >= O_DIM) return;

    int r = o >> 2;
    int a = o & 3;
    const int* p = packed + (size_t)r * I_DIM + (iblk >> 1) * 64 + a * 16 + (iblk & 1) * 8;
    int4 w0 = *(const int4*)p;
    int4 w1 = *(const int4*)(p + 4);
    int regs[8] = {w0.x, w0.y, w0.z, w0.w, w1.x, w1.y, w1.z, w1.w};

    int g = iblk >> 2;
    float v1 = s1[(size_t)g * O_DIM + o];
    float v2 = s2[(size_t)g * O_DIM + o];
    // adjusted_zeros = -(scale*zp): sign bit set (incl -0.0); scales > 0
    bool v1_is_zero = (__float_as_uint(v1) >> 31) != 0u;
    float scale = v1_is_zero ? v2 : v1;
    float zero  = v1_is_zero ? v1 : v2;

    __half out[32];
#pragma unroll
    for (int c = 0; c < 32; ++c) {
        int reg = ((c >> 1) & 3) * 2 + (c & 1);
        int nib = (regs[reg] >> ((c >> 3) * 4)) & 15;
        out[c] = __float2half(fmaf((float)nib, scale, zero));
    }

    uint4* dst = (uint4*)(g_W + (size_t)o * I_DIM + iblk * 32);
    const uint4* src = (const uint4*)out;
    dst[0] = src[0]; dst[1] = src[1]; dst[2] = src[2]; dst[3] = src[3];
}

// ---------------------------------------------------------------------------
// GEMM: out[m,n] = fp16(sum_k x[m,k]*W[n,k]) + fp16(bias[n]), stored as fp32
// ---------------------------------------------------------------------------
__device__ __forceinline__ uint32_t smem_u32(const void* p) {
    return (uint32_t)__cvta_generic_to_shared(p);
}
__device__ __forceinline__ void cp_async16(void* dst, const void* src) {
    asm volatile("cp.async.cg.shared.global [%0], [%1], 16;\n"
                 :: "r"(smem_u32(dst)), "l"(src));
}
__device__ __forceinline__ void ldsm_x4(uint32_t& r0, uint32_t& r1, uint32_t& r2, uint32_t& r3,
                                        const void* p) {
    asm volatile("ldmatrix.sync.aligned.m8n8.x4.shared.b16 {%0,%1,%2,%3}, [%4];\n"
                 : "=r"(r0), "=r"(r1), "=r"(r2), "=r"(r3) : "r"(smem_u32(p)));
}
__device__ __forceinline__ void mma16816(float& c0, float& c1, float& c2, float& c3,
                                         uint32_t a0, uint32_t a1, uint32_t a2, uint32_t a3,
                                         uint32_t b0, uint32_t b1) {
    asm volatile("mma.sync.aligned.m16n8k16.row.col.f32.f16.f16.f32 "
                 "{%0,%1,%2,%3}, {%4,%5,%6,%7}, {%8,%9}, {%0,%1,%2,%3};\n"
                 : "+f"(c0), "+f"(c1), "+f"(c2), "+f"(c3)
                 : "r"(a0), "r"(a1), "r"(a2), "r"(a3), "r"(b0), "r"(b1));
}

__global__ void __launch_bounds__(256, 2)
gemm_kernel(const float* __restrict__ bias_in, float* __restrict__ out) {
    extern __shared__ __align__(16) char smem_raw[];

    const int tid  = threadIdx.x;
    const int lane = tid & 31;
    const int wid  = tid >> 5;
    const int wm   = wid & 1;   // 2 warps along M (64 rows)
    const int wn   = wid >> 1;  // 4 warps along N (32 cols)

    const int m0 = blockIdx.y * BM;
    const int n0 = blockIdx.x * BN;

    float acc[4][4][4];
#pragma unroll
    for (int i = 0; i < 4; ++i)
#pragma unroll
        for (int j = 0; j < 4; ++j)
#pragma unroll
            for (int k = 0; k < 4; ++k) acc[i][j][k] = 0.0f;

    auto tileA = [&](int buf) { return (__half*)(smem_raw + buf * STAGE_BYTES); };
    auto tileB = [&](int buf) { return (__half*)(smem_raw + buf * STAGE_BYTES + A_STAGE_BYTES); };

    auto load_A = [&](int kt, int buf) {
        int k0 = kt * BK;
        __half* A = tileA(buf);
#pragma unroll
        for (int l = 0; l < 4; ++l) {
            int idx = tid + l * 256;
            int row = idx >> 3;
            int cc  = idx & 7;
            cp_async16(A + row * ROWB + cc * 8,
                       g_x + (size_t)(m0 + row) * I_DIM + k0 + cc * 8);
        }
    };
    auto load_B = [&](int kt, int buf) {
        int k0 = kt * BK;
        __half* B = tileB(buf);
#pragma unroll
        for (int l = 0; l < 4; ++l) {
            int idx = tid + l * 256;
            int row = idx >> 3;
            int cc  = idx & 7;
            cp_async16(B + row * ROWB + cc * 8,
                       g_W + (size_t)(n0 + row) * I_DIM + k0 + cc * 8);
        }
    };

    // Prologue: fill stages 0..1
#pragma unroll
    for (int s = 0; s < STAGES - 1; ++s) {
        load_A(s, s);
        load_B(s, s);
        asm volatile("cp.async.commit_group;\n");
    }

    const int ksrot = wid & 3;           // stagger warps across k-slices
    const int mtrot = (wid >> 1) & 3;    // stagger A-row order per warp group

    int buf = 0;
    for (int kt = 0; kt < KT2; ++kt) {
        asm volatile("cp.async.wait_group %0;\n" :: "n"(STAGES - 2));
        __syncthreads();

        const __half* A = tileA(buf);
        const __half* B = tileB(buf);

        int nb = buf + (STAGES - 1);
        if (nb >= STAGES) nb -= STAGES;
        const bool do_load = (kt + STAGES - 1 < KT2);

#pragma unroll
        for (int kss = 0; kss < BK / 16; ++kss) {
            const int ks = (kss + ksrot) & 3;   // rotated k-slice order per warp

            uint32_t a[4][4];
#pragma unroll
            for (int mtt = 0; mtt < 4; ++mtt) {
                const int mt = (mtt + mtrot) & 3;
                const __half* p = A + (wm * 64 + mt * 16 + (lane & 15)) * ROWB
                                    + ks * 16 + (lane >> 4) * 8;
                ldsm_x4(a[mt][0], a[mt][1], a[mt][2], a[mt][3], p);
            }
            uint32_t b[2][4];
#pragma unroll
            for (int ntp = 0; ntp < 2; ++ntp) {
                int row = wn * 32 + ntp * 16 + ((lane >> 4) << 3) + (lane & 7);
                int col = ks * 16 + ((lane >> 3) & 1) * 8;
                const __half* p = B + row * ROWB + col;
                ldsm_x4(b[ntp][0], b[ntp][1], b[ntp][2], b[ntp][3], p);
            }
#pragma unroll
            for (int mtt = 0; mtt < 4; ++mtt) {
                const int mt = (mtt + mtrot) & 3;
#pragma unroll
                for (int ntp = 0; ntp < 2; ++ntp) {
                    mma16816(acc[mt][2 * ntp][0], acc[mt][2 * ntp][1],
                             acc[mt][2 * ntp][2], acc[mt][2 * ntp][3],
                             a[mt][0], a[mt][1], a[mt][2], a[mt][3],
                             b[ntp][0], b[ntp][1]);
                    mma16816(acc[mt][2 * ntp + 1][0], acc[mt][2 * ntp + 1][1],
                             acc[mt][2 * ntp + 1][2], acc[mt][2 * ntp + 1][3],
                             a[mt][0], a[mt][1], a[mt][2], a[mt][3],
                             b[ntp][2], b[ntp][3]);
                }
            }

            // Spread next-stage loads: A after slice 0, B after slice 1
            if (kss == 0 && do_load) load_A(kt + STAGES - 1, nb);
            if (kss == 1) {
                if (do_load) load_B(kt + STAGES - 1, nb);
                asm volatile("cp.async.commit_group;\n");
            }
        }
        if (++buf == STAGES) buf = 0;
    }

    // Epilogue: round acc to fp16, add fp16(bias) in fp16, upcast to fp32 store
#pragma unroll
    for (int mt = 0; mt < 4; ++mt) {
#pragma unroll
        for (int nt = 0; nt < 4; ++nt) {
            int m = m0 + wm * 64 + mt * 16 + (lane >> 2);
            int n = n0 + wn * 32 + nt * 8 + (lane & 3) * 2;
            __half b0h = __float2half(bias_in[n]);
            __half b1h = __float2half(bias_in[n + 1]);
            __half r00 = __hadd(__float2half(acc[mt][nt][0]), b0h);
            __half r01 = __hadd(__float2half(acc[mt][nt][1]), b1h);
            __half r10 = __hadd(__float2half(acc[mt][nt][2]), b0h);
            __half r11 = __hadd(__float2half(acc[mt][nt][3]), b1h);
            *(float2*)(out + (size_t)m * O_DIM + n) =
                make_float2(__half2float(r00), __half2float(r01));
            *(float2*)(out + (size_t)(m + 8) * O_DIM + n) =
                make_float2(__half2float(r10), __half2float(r11));
        }
    }
}

// ---------------------------------------------------------------------------
extern "C" void kernel_launch(void* const* d_in, const int* in_sizes, int n_in,
                              void* d_out, int out_size) {
    // Slot inputs by size rank (unit-agnostic): x > packed > {scales,zeros} > bias
    long long sz[16];
    int used[16], order[16];
    for (int i = 0; i < n_in && i < 16; ++i) { sz[i] = in_sizes[i]; used[i] = 0; }
    for (int r = 0; r < n_in && r < 16; ++r) {
        int best = -1;
        for (int i = 0; i < n_in && i < 16; ++i)
            if (!used[i] && (best < 0 || sz[i] > sz[best])) best = i;
        used[best] = 1;
        order[r] = best;
    }
    const float* x      = (const float*)d_in[order[0]];
    const int*   packed = (const int*)d_in[order[1]];
    const float* s1     = (const float*)d_in[order[2]];
    const float* s2     = (const float*)d_in[order[3]];
    const float* bias   = (const float*)d_in[order[n_in < 5 ? n_in - 1 : 4]];

    cudaFuncSetAttribute(gemm_kernel,
                         cudaFuncAttributeMaxDynamicSharedMemorySize, SMEM_TOTAL);

    prep_kernel<<<XSTAGE_BLOCKS + DQ_BLOCKS, 256>>>(x, packed, s1, s2);

    dim3 grid(O_DIM / BN, M_DIM / BM);  // (86, 64)
    gemm_kernel<<<grid, 256, SMEM_TOTAL>>>(bias, (float*)d_out);
}

// round 14
// speedup vs baseline: 9.9135x; 9.9135x over previous
#include <cuda_runtime.h>
#include <cuda_fp16.h>
#include <cstdint>

// Problem dims (LLaMA-7B up-proj, AWQ w4 g128)
#define O_DIM 11008
#define I_DIM 4096
#define M_DIM 8192   // B*S
#define X_ELEMS ((size_t)M_DIM * I_DIM)

// GEMM tiling: 128x128 CTA, 8 warps of 64x32, BK=64, 3 stages
#define BM 128
#define BN 128
#define BK 64
#define KT2 (I_DIM / BK)   // 64
#define PAD 8
#define STAGES 3
#define ROWB (BK + PAD)                       // 72 halves
#define A_STAGE_BYTES (BM * ROWB * 2)         // 18432
#define B_STAGE_BYTES (BN * ROWB * 2)         // 18432
#define STAGE_BYTES (A_STAGE_BYTES + B_STAGE_BYTES)   // 36864
#define SMEM_TOTAL (STAGES * STAGE_BYTES)     // 110592

// Prep kernel split: x-stage blocks then dequant blocks
#define XSTAGE_BLOCKS ((int)(X_ELEMS / 8 / 256))            // 16384
#define DQ_BLOCKS ((O_DIM * (I_DIM / 32)) / 256)            // 5504

// Scratch: dequantized weights (O,I) fp16, staged activations (M,K) fp16
static __device__ __half g_W[(size_t)O_DIM * I_DIM];
static __device__ __half g_x[X_ELEMS];

// ---------------------------------------------------------------------------
// Fused prep: x fp32->fp16 staging AND AWQ int4 dequant in one launch.
// ---------------------------------------------------------------------------
__global__ void __launch_bounds__(256)
prep_kernel(const float* __restrict__ xin,
            const int* __restrict__ packed,
            const float* __restrict__ s1,
            const float* __restrict__ s2) {
    if (blockIdx.x < XSTAGE_BLOCKS) {
        size_t i = ((size_t)blockIdx.x * 256 + threadIdx.x) * 8;
        const float4* p = (const float4*)(xin + i);
        float4 a = p[0], b = p[1];
        __half h[8] = {__float2half(a.x), __float2half(a.y), __float2half(a.z), __float2half(a.w),
                       __float2half(b.x), __float2half(b.y), __float2half(b.z), __float2half(b.w)};
        *(uint4*)(g_x + i) = *(const uint4*)h;
        return;
    }

    int gid = (blockIdx.x - XSTAGE_BLOCKS) * 256 + threadIdx.x;
    int o    = gid >> 7;
    int iblk = gid & 127;
    if (o >= O_DIM) return;

    int r = o >> 2;
    int a = o & 3;
    const int* p = packed + (size_t)r * I_DIM + (iblk >> 1) * 64 + a * 16 + (iblk & 1) * 8;
    int4 w0 = *(const int4*)p;
    int4 w1 = *(const int4*)(p + 4);
    int regs[8] = {w0.x, w0.y, w0.z, w0.w, w1.x, w1.y, w1.z, w1.w};

    int g = iblk >> 2;
    float v1 = s1[(size_t)g * O_DIM + o];
    float v2 = s2[(size_t)g * O_DIM + o];
    // adjusted_zeros = -(scale*zp): sign bit set (incl -0.0); scales > 0
    bool v1_is_zero = (__float_as_uint(v1) >> 31) != 0u;
    float scale = v1_is_zero ? v2 : v1;
    float zero  = v1_is_zero ? v1 : v2;

    __half out[32];
#pragma unroll
    for (int c = 0; c < 32; ++c) {
        int reg = ((c >> 1) & 3) * 2 + (c & 1);
        int nib = (regs[reg] >> ((c >> 3) * 4)) & 15;
        out[c] = __float2half(fmaf((float)nib, scale, zero));
    }

    uint4* dst = (uint4*)(g_W + (size_t)o * I_DIM + iblk * 32);
    const uint4* src = (const uint4*)out;
    dst[0] = src[0]; dst[1] = src[1]; dst[2] = src[2]; dst[3] = src[3];
}

// ---------------------------------------------------------------------------
// GEMM: out[m,n] = fp16(sum_k x[m,k]*W[n,k]) + fp16(bias[n]), stored as fp32
// ---------------------------------------------------------------------------
__device__ __forceinline__ uint32_t smem_u32(const void* p) {
    return (uint32_t)__cvta_generic_to_shared(p);
}
__device__ __forceinline__ void cp_async16(void* dst, const void* src) {
    asm volatile("cp.async.cg.shared.global [%0], [%1], 16;\n"
                 :: "r"(smem_u32(dst)), "l"(src));
}
__device__ __forceinline__ void ldsm_x4(uint32_t& r0, uint32_t& r1, uint32_t& r2, uint32_t& r3,
                                        const void* p) {
    asm volatile("ldmatrix.sync.aligned.m8n8.x4.shared.b16 {%0,%1,%2,%3}, [%4];\n"
                 : "=r"(r0), "=r"(r1), "=r"(r2), "=r"(r3) : "r"(smem_u32(p)));
}
__device__ __forceinline__ void mma16816(float& c0, float& c1, float& c2, float& c3,
                                         uint32_t a0, uint32_t a1, uint32_t a2, uint32_t a3,
                                         uint32_t b0, uint32_t b1) {
    asm volatile("mma.sync.aligned.m16n8k16.row.col.f32.f16.f16.f32 "
                 "{%0,%1,%2,%3}, {%4,%5,%6,%7}, {%8,%9}, {%0,%1,%2,%3};\n"
                 : "+f"(c0), "+f"(c1), "+f"(c2), "+f"(c3)
                 : "r"(a0), "r"(a1), "r"(a2), "r"(a3), "r"(b0), "r"(b1));
}

__global__ void __launch_bounds__(256, 2)
gemm_kernel(const float* __restrict__ bias_in, float* __restrict__ out) {
    extern __shared__ __align__(16) char smem_raw[];

    const int tid  = threadIdx.x;
    const int lane = tid & 31;
    const int wid  = tid >> 5;
    const int wm   = wid & 1;   // 2 warps along M (64 rows)
    const int wn   = wid >> 1;  // 4 warps along N (32 cols)

    const int m0 = blockIdx.y * BM;
    const int n0 = blockIdx.x * BN;

    float acc[4][4][4];
#pragma unroll
    for (int i = 0; i < 4; ++i)
#pragma unroll
        for (int j = 0; j < 4; ++j)
#pragma unroll
            for (int k = 0; k < 4; ++k) acc[i][j][k] = 0.0f;

    auto tileA = [&](int buf) { return (__half*)(smem_raw + buf * STAGE_BYTES); };
    auto tileB = [&](int buf) { return (__half*)(smem_raw + buf * STAGE_BYTES + A_STAGE_BYTES); };

    auto load_A = [&](int kt, int buf) {
        int k0 = kt * BK;
        __half* A = tileA(buf);
#pragma unroll
        for (int l = 0; l < 4; ++l) {
            int idx = tid + l * 256;
            int row = idx >> 3;
            int cc  = idx & 7;
            cp_async16(A + row * ROWB + cc * 8,
                       g_x + (size_t)(m0 + row) * I_DIM + k0 + cc * 8);
        }
    };
    auto load_B = [&](int kt, int buf) {
        int k0 = kt * BK;
        __half* B = tileB(buf);
#pragma unroll
        for (int l = 0; l < 4; ++l) {
            int idx = tid + l * 256;
            int row = idx >> 3;
            int cc  = idx & 7;
            cp_async16(B + row * ROWB + cc * 8,
                       g_W + (size_t)(n0 + row) * I_DIM + k0 + cc * 8);
        }
    };

    // Prologue: fill stages 0..1
#pragma unroll
    for (int s = 0; s < STAGES - 1; ++s) {
        load_A(s, s);
        load_B(s, s);
        asm volatile("cp.async.commit_group;\n");
    }

    const int ksrot = wid & 3;   // stagger warps across k-slices (address-only)

    int buf = 0;
    for (int kt = 0; kt < KT2; ++kt) {
        asm volatile("cp.async.wait_group %0;\n" :: "n"(STAGES - 2));
        __syncthreads();

        const __half* A = tileA(buf);
        const __half* B = tileB(buf);

        int nb = buf + (STAGES - 1);
        if (nb >= STAGES) nb -= STAGES;
        const bool do_load = (kt + STAGES - 1 < KT2);

#pragma unroll
        for (int kss = 0; kss < BK / 16; ++kss) {
            const int ks = (kss + ksrot) & 3;   // rotated k-slice order per warp

            uint32_t a[4][4];
#pragma unroll
            for (int mt = 0; mt < 4; ++mt) {    // STATIC register-array indices
                const __half* p = A + (wm * 64 + mt * 16 + (lane & 15)) * ROWB
                                    + ks * 16 + (lane >> 4) * 8;
                ldsm_x4(a[mt][0], a[mt][1], a[mt][2], a[mt][3], p);
            }
            uint32_t b[2][4];
#pragma unroll
            for (int ntp = 0; ntp < 2; ++ntp) {
                int row = wn * 32 + ntp * 16 + ((lane >> 4) << 3) + (lane & 7);
                int col = ks * 16 + ((lane >> 3) & 1) * 8;
                const __half* p = B + row * ROWB + col;
                ldsm_x4(b[ntp][0], b[ntp][1], b[ntp][2], b[ntp][3], p);
            }
#pragma unroll
            for (int mt = 0; mt < 4; ++mt)
#pragma unroll
                for (int ntp = 0; ntp < 2; ++ntp) {
                    mma16816(acc[mt][2 * ntp][0], acc[mt][2 * ntp][1],
                             acc[mt][2 * ntp][2], acc[mt][2 * ntp][3],
                             a[mt][0], a[mt][1], a[mt][2], a[mt][3],
                             b[ntp][0], b[ntp][1]);
                    mma16816(acc[mt][2 * ntp + 1][0], acc[mt][2 * ntp + 1][1],
                             acc[mt][2 * ntp + 1][2], acc[mt][2 * ntp + 1][3],
                             a[mt][0], a[mt][1], a[mt][2], a[mt][3],
                             b[ntp][2], b[ntp][3]);
                }

            // Spread next-stage loads: A after slice 0, B + commit after slice 1
            if (kss == 0 && do_load) load_A(kt + STAGES - 1, nb);
            if (kss == 1) {
                if (do_load) load_B(kt + STAGES - 1, nb);
                asm volatile("cp.async.commit_group;\n");
            }
        }
        if (++buf == STAGES) buf = 0;
    }

    // Epilogue: round acc to fp16, add fp16(bias) in fp16, upcast to fp32 store
#pragma unroll
    for (int mt = 0; mt < 4; ++mt) {
#pragma unroll
        for (int nt = 0; nt < 4; ++nt) {
            int m = m0 + wm * 64 + mt * 16 + (lane >> 2);
            int n = n0 + wn * 32 + nt * 8 + (lane & 3) * 2;
            __half b0h = __float2half(bias_in[n]);
            __half b1h = __float2half(bias_in[n + 1]);
            __half r00 = __hadd(__float2half(acc[mt][nt][0]), b0h);
            __half r01 = __hadd(__float2half(acc[mt][nt][1]), b1h);
            __half r10 = __hadd(__float2half(acc[mt][nt][2]), b0h);
            __half r11 = __hadd(__float2half(acc[mt][nt][3]), b1h);
            *(float2*)(out + (size_t)m * O_DIM + n) =
                make_float2(__half2float(r00), __half2float(r01));
            *(float2*)(out + (size_t)(m + 8) * O_DIM + n) =
                make_float2(__half2float(r10), __half2float(r11));
        }
    }
}

// ---------------------------------------------------------------------------
extern "C" void kernel_launch(void* const* d_in, const int* in_sizes, int n_in,
                              void* d_out, int out_size) {
    // Slot inputs by size rank (unit-agnostic): x > packed > {scales,zeros} > bias
    long long sz[16];
    int used[16], order[16];
    for (int i = 0; i < n_in && i < 16; ++i) { sz[i] = in_sizes[i]; used[i] = 0; }
    for (int r = 0; r < n_in && r < 16; ++r) {
        int best = -1;
        for (int i = 0; i < n_in && i < 16; ++i)
            if (!used[i] && (best < 0 || sz[i] > sz[best])) best = i;
        used[best] = 1;
        order[r] = best;
    }
    const float* x      = (const float*)d_in[order[0]];
    const int*   packed = (const int*)d_in[order[1]];
    const float* s1     = (const float*)d_in[order[2]];
    const float* s2     = (const float*)d_in[order[3]];
    const float* bias   = (const float*)d_in[order[n_in < 5 ? n_in - 1 : 4]];

    cudaFuncSetAttribute(gemm_kernel,
                         cudaFuncAttributeMaxDynamicSharedMemorySize, SMEM_TOTAL);

    prep_kernel<<<XSTAGE_BLOCKS + DQ_BLOCKS, 256>>>(x, packed, s1, s2);

    dim3 grid(O_DIM / BN, M_DIM / BM);  // (86, 64)
    gemm_kernel<<<grid, 256, SMEM_TOTAL>>>(bias, (float*)d_out);
}

// round 15
// speedup vs baseline: 10.0513x; 1.0139x over previous
#include <cuda_runtime.h>
#include <cuda_fp16.h>
#include <cstdint>

// Problem dims (LLaMA-7B up-proj, AWQ w4 g128)
#define O_DIM 11008
#define I_DIM 4096
#define M_DIM 8192   // B*S
#define X_ELEMS ((size_t)M_DIM * I_DIM)

// GEMM tiling: 128x128 CTA, 8 warps of 64x32, BK=64, 3 stages
#define BM 128
#define BN 128
#define BK 64
#define KT2 (I_DIM / BK)   // 64
#define PAD 8
#define STAGES 3
#define ROWB (BK + PAD)                       // 72 halves
#define A_STAGE_BYTES (BM * ROWB * 2)         // 18432
#define B_STAGE_BYTES (BN * ROWB * 2)         // 18432
#define STAGE_BYTES (A_STAGE_BYTES + B_STAGE_BYTES)   // 36864
#define SMEM_TOTAL (STAGES * STAGE_BYTES)     // 110592

// Prep kernel split: x-stage blocks then dequant blocks
#define XSTAGE_BLOCKS ((int)(X_ELEMS / 8 / 256))            // 16384
#define DQ_BLOCKS ((O_DIM * (I_DIM / 32)) / 256)            // 5504

// Scratch: dequantized weights (O,I) fp16, staged activations (M,K) fp16
static __device__ __half g_W[(size_t)O_DIM * I_DIM];
static __device__ __half g_x[X_ELEMS];

// ---------------------------------------------------------------------------
// Fused prep: x fp32->fp16 staging AND AWQ int4 dequant in one launch.
// ---------------------------------------------------------------------------
__global__ void __launch_bounds__(256)
prep_kernel(const float* __restrict__ xin,
            const int* __restrict__ packed,
            const float* __restrict__ s1,
            const float* __restrict__ s2) {
    if (blockIdx.x < XSTAGE_BLOCKS) {
        size_t i = ((size_t)blockIdx.x * 256 + threadIdx.x) * 8;
        const float4* p = (const float4*)(xin + i);
        float4 a = p[0], b = p[1];
        __half h[8] = {__float2half(a.x), __float2half(a.y), __float2half(a.z), __float2half(a.w),
                       __float2half(b.x), __float2half(b.y), __float2half(b.z), __float2half(b.w)};
        *(uint4*)(g_x + i) = *(const uint4*)h;
        return;
    }

    int gid = (blockIdx.x - XSTAGE_BLOCKS) * 256 + threadIdx.x;
    int o    = gid >> 7;
    int iblk = gid & 127;
    if (o >= O_DIM) return;

    int r = o >> 2;
    int a = o & 3;
    const int* p = packed + (size_t)r * I_DIM + (iblk >> 1) * 64 + a * 16 + (iblk & 1) * 8;
    int4 w0 = *(const int4*)p;
    int4 w1 = *(const int4*)(p + 4);
    int regs[8] = {w0.x, w0.y, w0.z, w0.w, w1.x, w1.y, w1.z, w1.w};

    int g = iblk >> 2;
    float v1 = s1[(size_t)g * O_DIM + o];
    float v2 = s2[(size_t)g * O_DIM + o];
    // adjusted_zeros = -(scale*zp): sign bit set (incl -0.0); scales > 0
    bool v1_is_zero = (__float_as_uint(v1) >> 31) != 0u;
    float scale = v1_is_zero ? v2 : v1;
    float zero  = v1_is_zero ? v1 : v2;

    __half out[32];
#pragma unroll
    for (int c = 0; c < 32; ++c) {
        int reg = ((c >> 1) & 3) * 2 + (c & 1);
        int nib = (regs[reg] >> ((c >> 3) * 4)) & 15;
        out[c] = __float2half(fmaf((float)nib, scale, zero));
    }

    uint4* dst = (uint4*)(g_W + (size_t)o * I_DIM + iblk * 32);
    const uint4* src = (const uint4*)out;
    dst[0] = src[0]; dst[1] = src[1]; dst[2] = src[2]; dst[3] = src[3];
}

// ---------------------------------------------------------------------------
// GEMM: out[m,n] = fp16(sum_k x[m,k]*W[n,k]) + fp16(bias[n]), stored as fp32
// ---------------------------------------------------------------------------
__device__ __forceinline__ uint32_t smem_u32(const void* p) {
    return (uint32_t)__cvta_generic_to_shared(p);
}
__device__ __forceinline__ void cp_async16(void* dst, const void* src) {
    asm volatile("cp.async.cg.shared.global [%0], [%1], 16;\n"
                 :: "r"(smem_u32(dst)), "l"(src));
}
__device__ __forceinline__ void ldsm_x4(uint32_t& r0, uint32_t& r1, uint32_t& r2, uint32_t& r3,
                                        const void* p) {
    asm volatile("ldmatrix.sync.aligned.m8n8.x4.shared.b16 {%0,%1,%2,%3}, [%4];\n"
                 : "=r"(r0), "=r"(r1), "=r"(r2), "=r"(r3) : "r"(smem_u32(p)));
}
__device__ __forceinline__ void mma16816(float& c0, float& c1, float& c2, float& c3,
                                         uint32_t a0, uint32_t a1, uint32_t a2, uint32_t a3,
                                         uint32_t b0, uint32_t b1) {
    asm volatile("mma.sync.aligned.m16n8k16.row.col.f32.f16.f16.f32 "
                 "{%0,%1,%2,%3}, {%4,%5,%6,%7}, {%8,%9}, {%0,%1,%2,%3};\n"
                 : "+f"(c0), "+f"(c1), "+f"(c2), "+f"(c3)
                 : "r"(a0), "r"(a1), "r"(a2), "r"(a3), "r"(b0), "r"(b1));
}

__global__ void __launch_bounds__(256, 2)
gemm_kernel(const float* __restrict__ bias_in, float* __restrict__ out) {
    extern __shared__ __align__(16) char smem_raw[];

    const int tid  = threadIdx.x;
    const int lane = tid & 31;
    const int wid  = tid >> 5;
    const int wm   = wid & 1;   // 2 warps along M (64 rows)
    const int wn   = wid >> 1;  // 4 warps along N (32 cols)

    const int m0 = blockIdx.y * BM;
    const int n0 = blockIdx.x * BN;

    float acc[4][4][4];
#pragma unroll
    for (int i = 0; i < 4; ++i)
#pragma unroll
        for (int j = 0; j < 4; ++j)
#pragma unroll
            for (int k = 0; k < 4; ++k) acc[i][j][k] = 0.0f;

    auto tileA = [&](int buf) { return (__half*)(smem_raw + buf * STAGE_BYTES); };
    auto tileB = [&](int buf) { return (__half*)(smem_raw + buf * STAGE_BYTES + A_STAGE_BYTES); };

    auto load_A = [&](int kt, int buf) {
        int k0 = kt * BK;
        __half* A = tileA(buf);
#pragma unroll
        for (int l = 0; l < 4; ++l) {
            int idx = tid + l * 256;
            int row = idx >> 3;
            int cc  = idx & 7;
            cp_async16(A + row * ROWB + cc * 8,
                       g_x + (size_t)(m0 + row) * I_DIM + k0 + cc * 8);
        }
    };
    // B split in two halves (64 rows each) to spread the LSU burst
    auto load_B_half = [&](int kt, int buf, int half) {
        int k0 = kt * BK;
        __half* B = tileB(buf);
#pragma unroll
        for (int l = 0; l < 2; ++l) {
            int idx = tid + (half * 2 + l) * 256;
            int row = idx >> 3;
            int cc  = idx & 7;
            cp_async16(B + row * ROWB + cc * 8,
                       g_W + (size_t)(n0 + row) * I_DIM + k0 + cc * 8);
        }
    };

    // Prologue: fill stages 0..1
#pragma unroll
    for (int s = 0; s < STAGES - 1; ++s) {
        load_A(s, s);
        load_B_half(s, s, 0);
        load_B_half(s, s, 1);
        asm volatile("cp.async.commit_group;\n");
    }

    const int ksrot = wid & 3;   // stagger warps across k-slices (address-only)

    int buf = 0;
    for (int kt = 0; kt < KT2; ++kt) {
        asm volatile("cp.async.wait_group %0;\n" :: "n"(STAGES - 2));
        __syncthreads();

        const __half* A = tileA(buf);
        const __half* B = tileB(buf);

        int nb = buf + (STAGES - 1);
        if (nb >= STAGES) nb -= STAGES;
        const bool do_load = (kt + STAGES - 1 < KT2);

#pragma unroll
        for (int kss = 0; kss < BK / 16; ++kss) {
            const int ks = (kss + ksrot) & 3;   // rotated k-slice order per warp

            // B fragments first (needed by every mt group)
            uint32_t b[2][4];
#pragma unroll
            for (int ntp = 0; ntp < 2; ++ntp) {
                int row = wn * 32 + ntp * 16 + ((lane >> 4) << 3) + (lane & 7);
                int col = ks * 16 + ((lane >> 3) & 1) * 8;
                const __half* p = B + row * ROWB + col;
                ldsm_x4(b[ntp][0], b[ntp][1], b[ntp][2], b[ntp][3], p);
            }

            // Interleave: per-mt A ldmatrix immediately before its 4 MMAs.
            // asm volatile order is preserved, so mt+1's LDSM issues while
            // mt's MMAs occupy the tensor pipe — hides LDS latency in-warp.
#pragma unroll
            for (int mt = 0; mt < 4; ++mt) {
                uint32_t a0, a1, a2, a3;
                const __half* p = A + (wm * 64 + mt * 16 + (lane & 15)) * ROWB
                                    + ks * 16 + (lane >> 4) * 8;
                ldsm_x4(a0, a1, a2, a3, p);
#pragma unroll
                for (int ntp = 0; ntp < 2; ++ntp) {
                    mma16816(acc[mt][2 * ntp][0], acc[mt][2 * ntp][1],
                             acc[mt][2 * ntp][2], acc[mt][2 * ntp][3],
                             a0, a1, a2, a3, b[ntp][0], b[ntp][1]);
                    mma16816(acc[mt][2 * ntp + 1][0], acc[mt][2 * ntp + 1][1],
                             acc[mt][2 * ntp + 1][2], acc[mt][2 * ntp + 1][3],
                             a0, a1, a2, a3, b[ntp][2], b[ntp][3]);
                }
            }

            // Spread next-stage loads: A after slice 0, B halves after 1 and 2
            if (kss == 0 && do_load) load_A(kt + STAGES - 1, nb);
            if (kss == 1 && do_load) load_B_half(kt + STAGES - 1, nb, 0);
            if (kss == 2) {
                if (do_load) load_B_half(kt + STAGES - 1, nb, 1);
                asm volatile("cp.async.commit_group;\n");
            }
        }
        if (++buf == STAGES) buf = 0;
    }

    // Epilogue: round acc to fp16, add fp16(bias) in fp16, upcast to fp32 store
#pragma unroll
    for (int mt = 0; mt < 4; ++mt) {
#pragma unroll
        for (int nt = 0; nt < 4; ++nt) {
            int m = m0 + wm * 64 + mt * 16 + (lane >> 2);
            int n = n0 + wn * 32 + nt * 8 + (lane & 3) * 2;
            __half b0h = __float2half(bias_in[n]);
            __half b1h = __float2half(bias_in[n + 1]);
            __half r00 = __hadd(__float2half(acc[mt][nt][0]), b0h);
            __half r01 = __hadd(__float2half(acc[mt][nt][1]), b1h);
            __half r10 = __hadd(__float2half(acc[mt][nt][2]), b0h);
            __half r11 = __hadd(__float2half(acc[mt][nt][3]), b1h);
            *(float2*)(out + (size_t)m * O_DIM + n) =
                make_float2(__half2float(r00), __half2float(r01));
            *(float2*)(out + (size_t)(m + 8) * O_DIM + n) =
                make_float2(__half2float(r10), __half2float(r11));
        }
    }
}

// ---------------------------------------------------------------------------
extern "C" void kernel_launch(void* const* d_in, const int* in_sizes, int n_in,
                              void* d_out, int out_size) {
    // Slot inputs by size rank (unit-agnostic): x > packed > {scales,zeros} > bias
    long long sz[16];
    int used[16], order[16];
    for (int i = 0; i < n_in && i < 16; ++i) { sz[i] = in_sizes[i]; used[i] = 0; }
    for (int r = 0; r < n_in && r < 16; ++r) {
        int best = -1;
        for (int i = 0; i < n_in && i < 16; ++i)
            if (!used[i] && (best < 0 || sz[i] > sz[best])) best = i;
        used[best] = 1;
        order[r] = best;
    }
    const float* x      = (const float*)d_in[order[0]];
    const int*   packed = (const int*)d_in[order[1]];
    const float* s1     = (const float*)d_in[order[2]];
    const float* s2     = (const float*)d_in[order[3]];
    const float* bias   = (const float*)d_in[order[n_in < 5 ? n_in - 1 : 4]];

    cudaFuncSetAttribute(gemm_kernel,
                         cudaFuncAttributeMaxDynamicSharedMemorySize, SMEM_TOTAL);

    prep_kernel<<<XSTAGE_BLOCKS + DQ_BLOCKS, 256>>>(x, packed, s1, s2);

    dim3 grid(O_DIM / BN, M_DIM / BM);  // (86, 64)
    gemm_kernel<<<grid, 256, SMEM_TOTAL>>>(bias, (float*)d_out);
}